// round 4
// baseline (speedup 1.0000x reference)
#include <cuda_runtime.h>

#define THREADS 64
#define ROWS    64
#define NNN     129

// ---- persistent device scratch ----
__device__ float        gPartI[512];
__device__ float        gPartN[512];
__device__ unsigned int gCount = 0;

__device__ __forceinline__ int pair_off(int i) {
    return NNN + i * (2 * NNN - i - 1) / 2;
}
__device__ __forceinline__ unsigned long long packpair(float a, float b) {
    unsigned long long r;
    asm("mov.b64 %0, {%1, %2};" : "=l"(r) : "f"(a), "f"(b));
    return r;
}
__device__ __forceinline__ void unpack2(unsigned long long v, float& a, float& b) {
    asm("mov.b64 {%0, %1}, %2;" : "=f"(a), "=f"(b) : "l"(v));
}
#define FMA2(acc, a, b) asm("fma.rn.f32x2 %0, %1, %2, %0;" : "+l"(acc) : "l"(a), "l"(b))

__device__ __forceinline__ float tanh_fast(float w) {
    float e, r;
    asm("ex2.approx.f32 %0, %1;" : "=f"(e) : "f"(w * 2.885390081777927f));
    asm("rcp.approx.f32 %0, %1;" : "=f"(r) : "f"(e + 1.0f));
    return fmaf(-2.0f, r, 1.0f);
}

// Shared layout (float offsets). All weight rows are k-major & contiguous so the
// inner loops read them warp-uniformly (pure broadcast, conflict-free).
#define OFF_WT   0        // 64 x 64  Wt[k][i]
#define OFF_GT   4096     // 64 x 64  Gt[k][i] = G[i][k]  (x<->t pair block)
#define OFF_M    8192     // 64 x 64  M[k][l]  (sym tt block, 0.5 off-diag)
#define OFF_B    12288
#define OFF_WY   12352
#define OFF_wy   12416
#define OFF_wlt  12480
#define OFF_wys  12544
#define OFF_MISC 12608    // [0]=wl[64], [1]=last-block flag
#define OFF_RED  12612    // 2 warps x 2
#define OFF_U    12624    // union: input stage (64x65) THEN d/s spill (64x129)
#define SMEM_FLOATS (OFF_U + 64 * NNN)
#define SMEM_BYTES  (SMEM_FLOATS * 4)

__global__ void __launch_bounds__(THREADS)
fused_kernel(const float* __restrict__ inps,
             const float* __restrict__ tw,
             const float* __restrict__ tb,
             const float* __restrict__ mw,
             float* __restrict__ out,
             int Bn) {
    extern __shared__ float sm[];
    const int t    = threadIdx.x;
    const int row0 = blockIdx.x * ROWS;

    // ---------------- prep: weights into smem ----------------
    for (int idx = t; idx < 64 * 65; idx += THREADS) {
        int k = idx / 65, c = idx - k * 65;
        float v = tw[idx];
        if (c < 64) sm[OFF_WT + k * 64 + c] = v;
        else        sm[OFF_WY + k] = v;
    }
    for (int idx = t; idx < 4096; idx += THREADS) {
        int k = idx >> 6, i = idx & 63;
        sm[OFF_GT + idx] = mw[pair_off(i) + 64 + k - i];
    }
    for (int idx = t; idx < 4096; idx += THREADS) {
        int k = idx >> 6, l = idx & 63;
        float v = 0.0f;
        if (k != l) {
            int a = k < l ? k : l;
            int b = k < l ? l : k;
            v = 0.5f * mw[pair_off(65 + a) + b - a - 1];
        }
        sm[OFF_M + idx] = v;
    }
    for (int idx = t; idx < 64; idx += THREADS) {
        sm[OFF_B   + idx] = tb[idx];
        sm[OFF_wy  + idx] = mw[pair_off(idx) + 63 - idx];
        sm[OFF_wlt + idx] = mw[65 + idx];
        sm[OFF_wys + idx] = mw[pair_off(64) + idx];
    }
    if (t == 0) sm[OFF_MISC] = mw[64];

    // inputs, coalesced copy (row stride 65 == natural layout)
    const float* gsrc = inps + (long)row0 * 65;
    for (int idx = t; idx < 64 * 65; idx += THREADS)
        sm[OFF_U + idx] = gsrc[idx];
    __syncthreads();

    // ---------------- per-thread row into registers ----------------
    const float* myX = sm + OFF_U + t * 65;
    unsigned long long x2[32];
#pragma unroll
    for (int j = 0; j < 32; j++)
        x2[j] = packpair(myX[2 * j], myX[2 * j + 1]);
    const float yv = myX[64];

    float accXW = 0.0f;
#pragma unroll
    for (int j = 0; j < 32; j++) {
        float xa, xb;
        unpack2(x2[j], xa, xb);
        accXW = fmaf(xa, sm[OFF_wy + 2 * j],     accXW);
        accXW = fmaf(xb, sm[OFF_wy + 2 * j + 1], accXW);
    }
    __syncthreads();   // everyone done reading the input stage before d/s overwrite

    float* myDS = sm + OFF_U + t * NNN;   // [0..63]=d, [64..127]=s, stride 129

    // ---------------- Phase A: per-k c & a, tanh, penalties ----------------
    float gz1 = 0.0f, accDW = 0.0f, accSW = 0.0f, accI = 0.0f, accN = 0.0f;
#pragma unroll 4
    for (int k = 0; k < 64; k++) {
        unsigned long long cacc = 0ULL, aacc = 0ULL;
        const ulonglong2* wA = reinterpret_cast<const ulonglong2*>(sm + OFF_WT + k * 64);
        const ulonglong2* wG = reinterpret_cast<const ulonglong2*>(sm + OFF_GT + k * 64);
#pragma unroll
        for (int jj = 0; jj < 16; jj++) {
            ulonglong2 a = wA[jj];
            ulonglong2 b = wG[jj];
            FMA2(cacc, x2[2 * jj],     a.x);
            FMA2(cacc, x2[2 * jj + 1], a.y);
            FMA2(aacc, x2[2 * jj],     b.x);
            FMA2(aacc, x2[2 * jj + 1], b.y);
        }
        float clo, chi, alo, ahi;
        unpack2(cacc, clo, chi);
        unpack2(aacc, alo, ahi);
        float cv = clo + chi + sm[OFF_B + k];
        float av = alo + ahi;
        float hv = yv * sm[OFF_WY + k];
        float w1 = cv + hv;
        float w2 = cv - hv;
        float t1 = tanh_fast(w1);
        float t2 = tanh_fast(w2);
        float dk = t1 - t2;
        float sk = t1 + t2;
        myDS[k]      = dk;
        myDS[64 + k] = sk;
        gz1   = fmaf(dk, av, gz1);
        accDW = fmaf(dk, sm[OFF_wlt + k], accDW);
        accSW = fmaf(sk, sm[OFF_wys + k], accSW);
        float e1 = fmaf(-t1, t1, 1.0f);
        float e2 = fmaf(-t2, t2, 1.0f);
        accI = fmaf(e1, e1, accI);
        accI = fmaf(e2, e2, accI);
        float nt = fmaf(t2, w2, -(t1 * w1));
        accN = fmaf(nt, nt, accN);
    }

    // ---------------- Phase B: gz2 = d^T M s ----------------
    unsigned long long s2[32];
#pragma unroll
    for (int j = 0; j < 32; j++)
        s2[j] = packpair(myDS[64 + 2 * j], myDS[64 + 2 * j + 1]);

    float gz2 = 0.0f;
#pragma unroll 4
    for (int k = 0; k < 64; k++) {
        unsigned long long macc = 0ULL;
        const ulonglong2* wM = reinterpret_cast<const ulonglong2*>(sm + OFF_M + k * 64);
#pragma unroll
        for (int jj = 0; jj < 16; jj++) {
            ulonglong2 m = wM[jj];
            FMA2(macc, s2[2 * jj],     m.x);
            FMA2(macc, s2[2 * jj + 1], m.y);
        }
        float mlo, mhi;
        unpack2(macc, mlo, mhi);
        gz2 = fmaf(myDS[k], mlo + mhi, gz2);
    }

    float diff = 1.0f
               + 2.0f * yv * sm[OFF_MISC]
               + accDW
               + 2.0f * yv * accXW
               + yv * accSW
               + gz1 + gz2;
    out[row0 + t] = diff;

    // ---------------- penalty reduction ----------------
#pragma unroll
    for (int off = 16; off > 0; off >>= 1) {
        accI += __shfl_xor_sync(0xffffffffu, accI, off);
        accN += __shfl_xor_sync(0xffffffffu, accN, off);
    }
    if ((t & 31) == 0) {
        sm[OFF_RED + (t >> 5)]     = accI;
        sm[OFF_RED + 2 + (t >> 5)] = accN;
    }
    __syncthreads();
    if (t == 0) {
        gPartI[blockIdx.x] = sm[OFF_RED] + sm[OFF_RED + 1];
        gPartN[blockIdx.x] = sm[OFF_RED + 2] + sm[OFF_RED + 3];
        __threadfence();
        unsigned int tk = atomicAdd(&gCount, 1u);
        sm[OFF_MISC + 1] = (tk == gridDim.x - 1) ? 1.0f : 0.0f;
    }
    __syncthreads();

    if (sm[OFF_MISC + 1] != 0.0f && t < 32) {
        __threadfence();
        double sI = 0.0, sN = 0.0;
        for (int i = t; i < (int)gridDim.x; i += 32) {
            sI += (double)gPartI[i];
            sN += (double)gPartN[i];
        }
#pragma unroll
        for (int off = 16; off > 0; off >>= 1) {
            sI += __shfl_xor_sync(0xffffffffu, sI, off);
            sN += __shfl_xor_sync(0xffffffffu, sN, off);
        }
        if (t == 0) {
            out[Bn]     = (float)(sI * (1.0 / 300.0));
            out[Bn + 1] = (float)sN;
            gCount = 0;   // reset for next graph replay
        }
    }
}

extern "C" void kernel_launch(void* const* d_in, const int* in_sizes, int n_in,
                              void* d_out, int out_size) {
    const float* inps = (const float*)d_in[0];
    const float* tw   = (const float*)d_in[1];
    const float* tb   = (const float*)d_in[2];
    const float* mw   = (const float*)d_in[3];
    float* out = (float*)d_out;

    int Bn = in_sizes[0] / 65;

    cudaFuncSetAttribute(fused_kernel,
                         cudaFuncAttributeMaxDynamicSharedMemorySize, SMEM_BYTES);

    fused_kernel<<<Bn / ROWS, THREADS, SMEM_BYTES>>>(inps, tw, tb, mw, out, Bn);
}

// round 5
// speedup vs baseline: 2.1305x; 2.1305x over previous
#include <cuda_runtime.h>

#define THREADS 128
#define ROWS    64
#define NNN     129

// ---- persistent device scratch ----
__device__ float        gPartI[512];
__device__ float        gPartN[512];
__device__ unsigned int gCount = 0;

__device__ __forceinline__ int pair_off(int i) {
    return NNN + i * (2 * NNN - i - 1) / 2;
}
__device__ __forceinline__ unsigned long long packpair(float a, float b) {
    unsigned long long r;
    asm("mov.b64 %0, {%1, %2};" : "=l"(r) : "f"(a), "f"(b));
    return r;
}
__device__ __forceinline__ void unpack2(unsigned long long v, float& a, float& b) {
    asm("mov.b64 {%0, %1}, %2;" : "=f"(a), "=f"(b) : "l"(v));
}
#define FMA2(acc, a, b) asm("fma.rn.f32x2 %0, %1, %2, %0;" : "+l"(acc) : "l"(a), "l"(b))

__device__ __forceinline__ float tanh_fast(float w) {
    float e, r;
    asm("ex2.approx.f32 %0, %1;" : "=f"(e) : "f"(w * 2.885390081777927f));
    asm("rcp.approx.f32 %0, %1;" : "=f"(r) : "f"(e + 1.0f));
    return fmaf(-2.0f, r, 1.0f);
}

// Shared layout (float offsets). Weight rows k-major & contiguous: all weight
// reads are warp-uniform (every lane in a warp shares the same k) -> pure
// broadcast, 1 crossbar phase per LDS.128.
#define OFF_WT   0        // 64 x 64  Wt[k][i]
#define OFF_GT   4096     // 64 x 64  Gt[k][i]
#define OFF_M    8192     // 64 x 64  M[k][l]
#define OFF_B    12288
#define OFF_WY   12352
#define OFF_wy   12416
#define OFF_wlt  12480
#define OFF_wys  12544
#define OFF_MISC 12608    // [0]=wl[64], [1]=last-block flag
#define OFF_RED  12612    // 4 warps x 2
#define OFF_PART 12624    // 64 x 3 partner partials (gz, accDW, accSW)
#define OFF_DS   12816    // union: input stage (64x65) THEN d/s (64 rows x 129)
#define SMEM_FLOATS (OFF_DS + ROWS * NNN)
#define SMEM_BYTES  (SMEM_FLOATS * 4)

__global__ void __launch_bounds__(THREADS, 2)
fused_kernel(const float* __restrict__ inps,
             const float* __restrict__ tw,
             const float* __restrict__ tb,
             const float* __restrict__ mw,
             float* __restrict__ out,
             int Bn) {
    extern __shared__ float sm[];
    const int t    = threadIdx.x;
    const int r    = t & 63;          // row 0..63
    const int q    = t >> 6;          // k-half (uniform per warp)
    const int kb   = q * 32;
    const int row0 = blockIdx.x * ROWS;

    // ---------------- prep: weights into smem ----------------
    for (int idx = t; idx < 64 * 65; idx += THREADS) {
        int k = idx / 65, c = idx - k * 65;
        float v = tw[idx];
        if (c < 64) sm[OFF_WT + k * 64 + c] = v;
        else        sm[OFF_WY + k] = v;
    }
    for (int idx = t; idx < 4096; idx += THREADS) {
        int k = idx >> 6, i = idx & 63;
        sm[OFF_GT + idx] = mw[pair_off(i) + 64 + k - i];
    }
    for (int idx = t; idx < 4096; idx += THREADS) {
        int k = idx >> 6, l = idx & 63;
        float v = 0.0f;
        if (k != l) {
            int a = k < l ? k : l;
            int b = k < l ? l : k;
            v = 0.5f * mw[pair_off(65 + a) + b - a - 1];
        }
        sm[OFF_M + idx] = v;
    }
    for (int idx = t; idx < 64; idx += THREADS) {
        sm[OFF_B   + idx] = tb[idx];
        sm[OFF_wy  + idx] = mw[pair_off(idx) + 63 - idx];
        sm[OFF_wlt + idx] = mw[65 + idx];
        sm[OFF_wys + idx] = mw[pair_off(64) + idx];
    }
    if (t == 0) sm[OFF_MISC] = mw[64];

    // input stage (coalesced)
    const float* gsrc = inps + (long)row0 * 65;
    for (int idx = t; idx < 64 * 65; idx += THREADS)
        sm[OFF_DS + idx] = gsrc[idx];
    __syncthreads();

    // ---------------- full row x into registers ----------------
    const float* myX = sm + OFF_DS + r * 65;   // stride 65 -> conflict-free scalars
    unsigned long long x2[32];
#pragma unroll
    for (int j = 0; j < 32; j++)
        x2[j] = packpair(myX[2 * j], myX[2 * j + 1]);
    const float yv = myX[64];

    float accXW = 0.0f;   // full-row dot (q=0 copy is used at combine)
#pragma unroll
    for (int j = 0; j < 32; j++) {
        float xa, xb;
        unpack2(x2[j], xa, xb);
        accXW = fmaf(xa, sm[OFF_wy + 2 * j],     accXW);
        accXW = fmaf(xb, sm[OFF_wy + 2 * j + 1], accXW);
    }
    __syncthreads();   // stage fully consumed before d/s overwrite

    float* myDS = sm + OFF_DS + r * NNN;   // d at [k], s at [64+k]

    // ---------------- Phase A: own k-half ----------------
    float gz1 = 0.0f, accDW = 0.0f, accSW = 0.0f, accI = 0.0f, accN = 0.0f;
#pragma unroll 4
    for (int kk = 0; kk < 32; kk++) {
        int k = kb + kk;
        unsigned long long cacc = 0ULL, aacc = 0ULL;
        const ulonglong2* wA = reinterpret_cast<const ulonglong2*>(sm + OFF_WT + k * 64);
        const ulonglong2* wG = reinterpret_cast<const ulonglong2*>(sm + OFF_GT + k * 64);
#pragma unroll
        for (int jj = 0; jj < 16; jj++) {
            ulonglong2 a = wA[jj];
            ulonglong2 b = wG[jj];
            FMA2(cacc, x2[2 * jj],     a.x);
            FMA2(cacc, x2[2 * jj + 1], a.y);
            FMA2(aacc, x2[2 * jj],     b.x);
            FMA2(aacc, x2[2 * jj + 1], b.y);
        }
        float clo, chi, alo, ahi;
        unpack2(cacc, clo, chi);
        unpack2(aacc, alo, ahi);
        float cv = clo + chi + sm[OFF_B + k];
        float av = alo + ahi;
        float hv = yv * sm[OFF_WY + k];
        float w1 = cv + hv;
        float w2 = cv - hv;
        float t1 = tanh_fast(w1);
        float t2 = tanh_fast(w2);
        float dk = t1 - t2;
        float sk = t1 + t2;
        myDS[k]      = dk;
        myDS[64 + k] = sk;
        gz1   = fmaf(dk, av, gz1);
        accDW = fmaf(dk, sm[OFF_wlt + k], accDW);
        accSW = fmaf(sk, sm[OFF_wys + k], accSW);
        float e1 = fmaf(-t1, t1, 1.0f);
        float e2 = fmaf(-t2, t2, 1.0f);
        accI = fmaf(e1, e1, accI);
        accI = fmaf(e2, e2, accI);
        float nt = fmaf(t2, w2, -(t1 * w1));
        accN = fmaf(nt, nt, accN);
    }
    __syncthreads();   // both k-halves of s written

    // ---------------- Phase B: gz2 = sum_k d_k (M s)_k over own half ----------------
    unsigned long long s2[32];
#pragma unroll
    for (int j = 0; j < 32; j++)
        s2[j] = packpair(myDS[64 + 2 * j], myDS[64 + 2 * j + 1]);

    float gz2 = 0.0f;
#pragma unroll 4
    for (int kk = 0; kk < 32; kk++) {
        int k = kb + kk;
        unsigned long long macc = 0ULL;
        const ulonglong2* wM = reinterpret_cast<const ulonglong2*>(sm + OFF_M + k * 64);
#pragma unroll
        for (int jj = 0; jj < 16; jj++) {
            ulonglong2 m = wM[jj];
            FMA2(macc, s2[2 * jj],     m.x);
            FMA2(macc, s2[2 * jj + 1], m.y);
        }
        float mlo, mhi;
        unpack2(macc, mlo, mhi);
        gz2 = fmaf(myDS[k], mlo + mhi, gz2);
    }

    // ---------------- combine the two k-half threads ----------------
    float gz = gz1 + gz2;
    if (q == 1) {
        sm[OFF_PART + r]        = gz;
        sm[OFF_PART + 64 + r]   = accDW;
        sm[OFF_PART + 128 + r]  = accSW;
    }
    __syncthreads();
    if (q == 0) {
        float diff = 1.0f
                   + 2.0f * yv * sm[OFF_MISC]
                   + (accDW + sm[OFF_PART + 64 + r])
                   + 2.0f * yv * accXW
                   + yv * (accSW + sm[OFF_PART + 128 + r])
                   + gz + sm[OFF_PART + r];
        out[row0 + r] = diff;
    }

    // ---------------- penalty reduction ----------------
#pragma unroll
    for (int off = 16; off > 0; off >>= 1) {
        accI += __shfl_xor_sync(0xffffffffu, accI, off);
        accN += __shfl_xor_sync(0xffffffffu, accN, off);
    }
    if ((t & 31) == 0) {
        sm[OFF_RED + (t >> 5)]     = accI;
        sm[OFF_RED + 4 + (t >> 5)] = accN;
    }
    __syncthreads();
    if (t == 0) {
        float pI = 0.0f, pN = 0.0f;
#pragma unroll
        for (int w = 0; w < 4; w++) { pI += sm[OFF_RED + w]; pN += sm[OFF_RED + 4 + w]; }
        gPartI[blockIdx.x] = pI;
        gPartN[blockIdx.x] = pN;
        __threadfence();
        unsigned int tk = atomicAdd(&gCount, 1u);
        sm[OFF_MISC + 1] = (tk == gridDim.x - 1) ? 1.0f : 0.0f;
    }
    __syncthreads();

    if (sm[OFF_MISC + 1] != 0.0f && t < 32) {
        __threadfence();
        double sI = 0.0, sN = 0.0;
        for (int i = t; i < (int)gridDim.x; i += 32) {
            sI += (double)gPartI[i];
            sN += (double)gPartN[i];
        }
#pragma unroll
        for (int off = 16; off > 0; off >>= 1) {
            sI += __shfl_xor_sync(0xffffffffu, sI, off);
            sN += __shfl_xor_sync(0xffffffffu, sN, off);
        }
        if (t == 0) {
            out[Bn]     = (float)(sI * (1.0 / 300.0));
            out[Bn + 1] = (float)sN;
            gCount = 0;   // reset for next graph replay
        }
    }
}

extern "C" void kernel_launch(void* const* d_in, const int* in_sizes, int n_in,
                              void* d_out, int out_size) {
    const float* inps = (const float*)d_in[0];
    const float* tw   = (const float*)d_in[1];
    const float* tb   = (const float*)d_in[2];
    const float* mw   = (const float*)d_in[3];
    float* out = (float*)d_out;

    int Bn = in_sizes[0] / 65;

    cudaFuncSetAttribute(fused_kernel,
                         cudaFuncAttributeMaxDynamicSharedMemorySize, SMEM_BYTES);

    fused_kernel<<<Bn / ROWS, THREADS, SMEM_BYTES>>>(inps, tw, tb, mw, out, Bn);
}

// round 6
// speedup vs baseline: 2.1517x; 1.0100x over previous
#include <cuda_runtime.h>

#define THREADS 128
#define ROWS    64
#define NNN     129

// Prep block layout (floats) — identical in gPrep and shared memory:
#define OFF_WT   0        // 64 x 64  Wt[k][i]
#define OFF_GT   4096     // 64 x 64  Gt[k][i]
#define OFF_M    8192     // 64 x 64  M[k][l]
#define OFF_B    12288
#define OFF_WY   12352
#define OFF_wy   12416
#define OFF_wlt  12480
#define OFF_wys  12544
#define OFF_MISC 12608    // [0]=wl[64]
#define PREP_FLOATS 12624 // padded to /4

// shared-only extras
#define OFF_RED  12624    // 4 warps x 2
#define OFF_PART 12632    // 64 x 3 partner partials
#define OFF_FLAG 12824
#define OFF_DS   12832    // union: input stage (64x65) THEN d/s (64 x 129)
#define SMEM_FLOATS (OFF_DS + ROWS * NNN)
#define SMEM_BYTES  (SMEM_FLOATS * 4)

// ---- persistent device scratch ----
__device__ float        gPrep[PREP_FLOATS];
__device__ float        gPartI[512];
__device__ float        gPartN[512];
__device__ unsigned int gCount = 0;

__device__ __forceinline__ int pair_off(int i) {
    return NNN + i * (2 * NNN - i - 1) / 2;
}
__device__ __forceinline__ unsigned long long packpair(float a, float b) {
    unsigned long long r;
    asm("mov.b64 %0, {%1, %2};" : "=l"(r) : "f"(a), "f"(b));
    return r;
}
__device__ __forceinline__ void unpack2(unsigned long long v, float& a, float& b) {
    asm("mov.b64 {%0, %1}, %2;" : "=f"(a), "=f"(b) : "l"(v));
}
#define FMA2(acc, a, b) asm("fma.rn.f32x2 %0, %1, %2, %0;" : "+l"(acc) : "l"(a), "l"(b))

__device__ __forceinline__ float tanh_fast(float w) {
    float e, r;
    asm("ex2.approx.f32 %0, %1;" : "=f"(e) : "f"(w * 2.885390081777927f));
    asm("rcp.approx.f32 %0, %1;" : "=f"(r) : "f"(e + 1.0f));
    return fmaf(-2.0f, r, 1.0f);
}

// ---------------------------------------------------------------------------
// Prep kernel: derive all weight structures once, contiguous, final layout.
// ---------------------------------------------------------------------------
__global__ void prep_kernel(const float* __restrict__ tw,
                            const float* __restrict__ tb,
                            const float* __restrict__ mw) {
    int tid = blockIdx.x * blockDim.x + threadIdx.x;
    if (tid >= PREP_FLOATS) return;
    float v = 0.0f;
    if (tid < 4096) {                       // Wt[k][i]
        int k = tid >> 6, i = tid & 63;
        v = tw[k * 65 + i];
    } else if (tid < 8192) {                // Gt[k][i]
        int idx = tid - 4096;
        int k = idx >> 6, i = idx & 63;
        v = mw[pair_off(i) + 64 + k - i];
    } else if (tid < 12288) {               // M[k][l]
        int idx = tid - 8192;
        int k = idx >> 6, l = idx & 63;
        if (k != l) {
            int a = k < l ? k : l;
            int b = k < l ? l : k;
            v = 0.5f * mw[pair_off(65 + a) + b - a - 1];
        }
    } else if (tid < 12352) {               // B
        v = tb[tid - 12288];
    } else if (tid < 12416) {               // WY
        int k = tid - 12352;
        v = tw[k * 65 + 64];
    } else if (tid < 12480) {               // wy
        int i = tid - 12416;
        v = mw[pair_off(i) + 63 - i];
    } else if (tid < 12544) {               // wlt
        v = mw[65 + (tid - 12480)];
    } else if (tid < 12608) {               // wys
        v = mw[pair_off(64) + (tid - 12544)];
    } else if (tid == 12608) {              // misc: wl[64]
        v = mw[64];
    }
    gPrep[tid] = v;
    if (tid == 0) gCount = 0;
}

// ---------------------------------------------------------------------------
// Main kernel
// ---------------------------------------------------------------------------
__global__ void __launch_bounds__(THREADS, 2)
fused_kernel(const float* __restrict__ inps,
             float* __restrict__ out,
             int Bn) {
    extern __shared__ float sm[];
    const int t    = threadIdx.x;
    const int r    = t & 63;          // row 0..63
    const int q    = t >> 6;          // k-half (uniform per warp)
    const int kb   = q * 32;
    const int row0 = blockIdx.x * ROWS;

    // coalesced weight copy (L2-hot after first block)
    {
        const float4* src = reinterpret_cast<const float4*>(gPrep);
        float4* dst = reinterpret_cast<float4*>(sm);
        for (int idx = t; idx < PREP_FLOATS / 4; idx += THREADS)
            dst[idx] = src[idx];
    }
    // coalesced input stage
    {
        const float4* src = reinterpret_cast<const float4*>(inps + (long)row0 * 65);
        float4* dst = reinterpret_cast<float4*>(sm + OFF_DS);
        for (int idx = t; idx < (ROWS * 65) / 4; idx += THREADS)
            dst[idx] = src[idx];
    }
    __syncthreads();

    // ---------------- full row x into registers ----------------
    const float* myX = sm + OFF_DS + r * 65;
    unsigned long long x2[32];
#pragma unroll
    for (int j = 0; j < 32; j++)
        x2[j] = packpair(myX[2 * j], myX[2 * j + 1]);
    const float yv = myX[64];

    float accXW = 0.0f;
#pragma unroll
    for (int j = 0; j < 32; j++) {
        float xa, xb;
        unpack2(x2[j], xa, xb);
        accXW = fmaf(xa, sm[OFF_wy + 2 * j],     accXW);
        accXW = fmaf(xb, sm[OFF_wy + 2 * j + 1], accXW);
    }
    __syncthreads();   // stage fully consumed before d/s overwrite

    float* myDS = sm + OFF_DS + r * NNN;   // d at [k], s at [64+k]

    // ---------------- Phase A: own k-half ----------------
    float gz1 = 0.0f, accDW = 0.0f, accSW = 0.0f, accI = 0.0f, accN = 0.0f;
#pragma unroll 4
    for (int kk = 0; kk < 32; kk++) {
        int k = kb + kk;
        unsigned long long c0 = 0ULL, c1 = 0ULL, a0 = 0ULL, a1 = 0ULL;
        const ulonglong2* wA = reinterpret_cast<const ulonglong2*>(sm + OFF_WT + k * 64);
        const ulonglong2* wG = reinterpret_cast<const ulonglong2*>(sm + OFF_GT + k * 64);
#pragma unroll
        for (int jj = 0; jj < 16; jj += 2) {
            ulonglong2 A0 = wA[jj], A1 = wA[jj + 1];
            ulonglong2 B0 = wG[jj], B1 = wG[jj + 1];
            FMA2(c0, x2[2 * jj],     A0.x);
            FMA2(c0, x2[2 * jj + 1], A0.y);
            FMA2(c1, x2[2 * jj + 2], A1.x);
            FMA2(c1, x2[2 * jj + 3], A1.y);
            FMA2(a0, x2[2 * jj],     B0.x);
            FMA2(a0, x2[2 * jj + 1], B0.y);
            FMA2(a1, x2[2 * jj + 2], B1.x);
            FMA2(a1, x2[2 * jj + 3], B1.y);
        }
        float c0a, c0b, c1a, c1b, a0a, a0b, a1a, a1b;
        unpack2(c0, c0a, c0b); unpack2(c1, c1a, c1b);
        unpack2(a0, a0a, a0b); unpack2(a1, a1a, a1b);
        float cv = (c0a + c0b) + (c1a + c1b) + sm[OFF_B + k];
        float av = (a0a + a0b) + (a1a + a1b);
        float hv = yv * sm[OFF_WY + k];
        float w1 = cv + hv;
        float w2 = cv - hv;
        float t1 = tanh_fast(w1);
        float t2 = tanh_fast(w2);
        float dk = t1 - t2;
        float sk = t1 + t2;
        myDS[k]      = dk;
        myDS[64 + k] = sk;
        gz1   = fmaf(dk, av, gz1);
        accDW = fmaf(dk, sm[OFF_wlt + k], accDW);
        accSW = fmaf(sk, sm[OFF_wys + k], accSW);
        float e1 = fmaf(-t1, t1, 1.0f);
        float e2 = fmaf(-t2, t2, 1.0f);
        accI = fmaf(e1, e1, accI);
        accI = fmaf(e2, e2, accI);
        float nt = fmaf(t2, w2, -(t1 * w1));
        accN = fmaf(nt, nt, accN);
    }
    __syncthreads();   // both k-halves of s written

    // ---------------- Phase B: gz2 = sum_{k in half} d_k (M s)_k ----------------
    unsigned long long s2[32];
#pragma unroll
    for (int j = 0; j < 32; j++)
        s2[j] = packpair(myDS[64 + 2 * j], myDS[64 + 2 * j + 1]);

    float gz2 = 0.0f;
#pragma unroll 4
    for (int kk = 0; kk < 32; kk++) {
        int k = kb + kk;
        unsigned long long m0 = 0ULL, m1 = 0ULL;
        const ulonglong2* wM = reinterpret_cast<const ulonglong2*>(sm + OFF_M + k * 64);
#pragma unroll
        for (int jj = 0; jj < 16; jj += 2) {
            ulonglong2 M0 = wM[jj], M1 = wM[jj + 1];
            FMA2(m0, s2[2 * jj],     M0.x);
            FMA2(m0, s2[2 * jj + 1], M0.y);
            FMA2(m1, s2[2 * jj + 2], M1.x);
            FMA2(m1, s2[2 * jj + 3], M1.y);
        }
        float m0a, m0b, m1a, m1b;
        unpack2(m0, m0a, m0b); unpack2(m1, m1a, m1b);
        gz2 = fmaf(myDS[k], (m0a + m0b) + (m1a + m1b), gz2);
    }

    // ---------------- combine the two k-half threads ----------------
    float gz = gz1 + gz2;
    if (q == 1) {
        sm[OFF_PART + r]       = gz;
        sm[OFF_PART + 64 + r]  = accDW;
        sm[OFF_PART + 128 + r] = accSW;
    }
    __syncthreads();
    if (q == 0) {
        float diff = 1.0f
                   + 2.0f * yv * sm[OFF_MISC]
                   + (accDW + sm[OFF_PART + 64 + r])
                   + 2.0f * yv * accXW
                   + yv * (accSW + sm[OFF_PART + 128 + r])
                   + gz + sm[OFF_PART + r];
        out[row0 + r] = diff;
    }

    // ---------------- penalty reduction ----------------
#pragma unroll
    for (int off = 16; off > 0; off >>= 1) {
        accI += __shfl_xor_sync(0xffffffffu, accI, off);
        accN += __shfl_xor_sync(0xffffffffu, accN, off);
    }
    if ((t & 31) == 0) {
        sm[OFF_RED + (t >> 5)]     = accI;
        sm[OFF_RED + 4 + (t >> 5)] = accN;
    }
    __syncthreads();
    if (t == 0) {
        float pI = 0.0f, pN = 0.0f;
#pragma unroll
        for (int w = 0; w < 4; w++) { pI += sm[OFF_RED + w]; pN += sm[OFF_RED + 4 + w]; }
        gPartI[blockIdx.x] = pI;
        gPartN[blockIdx.x] = pN;
        __threadfence();
        unsigned int tk = atomicAdd(&gCount, 1u);
        sm[OFF_FLAG] = (tk == gridDim.x - 1) ? 1.0f : 0.0f;
    }
    __syncthreads();

    if (sm[OFF_FLAG] != 0.0f && t < 32) {
        __threadfence();
        double sI = 0.0, sN = 0.0;
        for (int i = t; i < (int)gridDim.x; i += 32) {
            sI += (double)gPartI[i];
            sN += (double)gPartN[i];
        }
#pragma unroll
        for (int off = 16; off > 0; off >>= 1) {
            sI += __shfl_xor_sync(0xffffffffu, sI, off);
            sN += __shfl_xor_sync(0xffffffffu, sN, off);
        }
        if (t == 0) {
            out[Bn]     = (float)(sI * (1.0 / 300.0));
            out[Bn + 1] = (float)sN;
            gCount = 0;   // reset for next graph replay
        }
    }
}

extern "C" void kernel_launch(void* const* d_in, const int* in_sizes, int n_in,
                              void* d_out, int out_size) {
    const float* inps = (const float*)d_in[0];
    const float* tw   = (const float*)d_in[1];
    const float* tb   = (const float*)d_in[2];
    const float* mw   = (const float*)d_in[3];
    float* out = (float*)d_out;

    int Bn = in_sizes[0] / 65;

    cudaFuncSetAttribute(fused_kernel,
                         cudaFuncAttributeMaxDynamicSharedMemorySize, SMEM_BYTES);

    prep_kernel<<<(PREP_FLOATS + 255) / 256, 256>>>(tw, tb, mw);
    fused_kernel<<<Bn / ROWS, THREADS, SMEM_BYTES>>>(inps, out, Bn);
}